// round 7
// baseline (speedup 1.0000x reference)
#include <cuda_runtime.h>
#include <math.h>

// Problem constants (fixed by setup_inputs)
#define NN    4096
#define INF_  256
#define SEG   512
#define HALF  64
#define WIN   128
#define NHEAD 4
#define HD    64
#define TOPK  32

// attention kernel tiling
#define NPB   32             // nodes per block
#define ATHR  1024           // attention threads per block (32 warps)
#define MAXR  160            // union window rows: (NPB-1)+128 = 159, pad to 160
#define KSTRB 276            // K smem row stride; 5*276 % 32 == 4 -> conflict-free 5-row stride
#define QROW  256
#define SROW  164            // score row stride

// GEMM tiling
#define GBM 64
#define GBN 64
#define GBK 16
#define GTHR 128
#define ASTR 68              // padded A-smem stride

// scratch: Q||K projections, [4096][512]  (cols 0..255 = Q, 256..511 = K)
__device__ float g_QK[(size_t)NN * 512];

// ---------------------------------------------------------------------------
// packed fp32x2 helpers (sm_100+: fma.rn.f32x2 — 2 IEEE fp32 FMAs per issue)
// ---------------------------------------------------------------------------
__device__ __forceinline__ void upk2(float& x, float& y, unsigned long long r) {
    asm("mov.b64 {%0, %1}, %2;" : "=f"(x), "=f"(y) : "l"(r));
}
__device__ __forceinline__ unsigned long long fma2(unsigned long long a,
                                                   unsigned long long b,
                                                   unsigned long long c) {
    unsigned long long d;
    asm("fma.rn.f32x2 %0, %1, %2, %3;" : "=l"(d) : "l"(a), "l"(b), "l"(c));
    return d;
}

// ---------------------------------------------------------------------------
// fused Q||K projection GEMM:  C[4096,512] = X[4096,256] @ [Wq|Wk] + [bq|bk]
// BM=64, BN=64, BK=16, 128 threads, 8x4 per thread. B stored DUPLICATED in
// smem so fp32x2 operand pairs come straight from LDS (no movs).
// Each block also zero-fills 128 KB (8 rows) of the output matrix.
// ---------------------------------------------------------------------------
__global__ __launch_bounds__(GTHR) void gemm_qk_kernel(
    const float* __restrict__ X,
    const float* __restrict__ Wq, const float* __restrict__ bq,
    const float* __restrict__ Wk, const float* __restrict__ bk,
    float4* __restrict__ out4)
{
    __shared__ float As[GBK][ASTR];       // transposed A tile [k][m]
    __shared__ float Bsd[GBK][2 * GBN];   // B tile, each value duplicated (b,b)

    const int tid = threadIdx.x;

    // ---- zero-fill slice of the output: block zb covers 8 rows (128 KB)
    {
        const int zb = blockIdx.y * gridDim.x + blockIdx.x;   // 0..511
        float4* zdst = out4 + (size_t)zb * (8 * NN / 4);
        const float4 z = make_float4(0.f, 0.f, 0.f, 0.f);
#pragma unroll
        for (int t = 0; t < (8 * NN / 4) / GTHR; t++)
            zdst[t * GTHR + tid] = z;
    }

    const int brow = blockIdx.y * GBM;
    const int bcol = blockIdx.x * GBN;

    // each block lies entirely in the Q half (bcol<256) or K half
    const float* W    = (bcol < 256) ? Wq : Wk;
    const float* bias = (bcol < 256) ? bq : bk;
    const int wcol = bcol & 255;

    const int tx = tid & 15;          // n0 = tx*4
    const int ty = tid >> 4;          // m0 = ty*8
    const int m0 = ty * 8;
    const int n0 = tx * 4;

    unsigned long long acc2[4][4];    // [m-pair][n]
#pragma unroll
    for (int a = 0; a < 4; a++)
#pragma unroll
        for (int b = 0; b < 4; b++) acc2[a][b] = 0ULL;

    for (int k0 = 0; k0 < INF_; k0 += GBK) {
        // load A tile 64x16 (256 float4, 2 per thread), transpose into As[k][m]
#pragma unroll
        for (int t = 0; t < 2; t++) {
            int f = tid + t * GTHR;
            int r = f >> 2;
            int c = (f & 3) << 2;
            float4 v = *(const float4*)(X + (size_t)(brow + r) * INF_ + k0 + c);
            As[c + 0][r] = v.x;
            As[c + 1][r] = v.y;
            As[c + 2][r] = v.z;
            As[c + 3][r] = v.w;
        }
        // load B tile 16x64, store duplicated pairs
#pragma unroll
        for (int t = 0; t < 2; t++) {
            int f = tid + t * GTHR;
            int r = f >> 4;
            int c = (f & 15) << 2;
            float4 v = *(const float4*)(W + (size_t)(k0 + r) * 256 + wcol + c);
            *(float4*)&Bsd[r][2 * c]     = make_float4(v.x, v.x, v.y, v.y);
            *(float4*)&Bsd[r][2 * c + 4] = make_float4(v.z, v.z, v.w, v.w);
        }
        __syncthreads();

#pragma unroll
        for (int k = 0; k < GBK; k++) {
            ulonglong2 a01 = *(const ulonglong2*)&As[k][m0];
            ulonglong2 a23 = *(const ulonglong2*)&As[k][m0 + 4];
            ulonglong2 b01 = *(const ulonglong2*)&Bsd[k][2 * n0];
            ulonglong2 b23 = *(const ulonglong2*)&Bsd[k][2 * n0 + 4];
            unsigned long long am[4] = {a01.x, a01.y, a23.x, a23.y};
            unsigned long long bd[4] = {b01.x, b01.y, b23.x, b23.y};
#pragma unroll
            for (int mp = 0; mp < 4; mp++)
#pragma unroll
                for (int n = 0; n < 4; n++)
                    acc2[mp][n] = fma2(am[mp], bd[n], acc2[mp][n]);
        }
        __syncthreads();
    }

    // epilogue: unpack, +bias, store two rows per m-pair
    float4 bv = *(const float4*)(bias + wcol + n0);
#pragma unroll
    for (int mp = 0; mp < 4; mp++) {
        float lo[4], hi[4];
#pragma unroll
        for (int n = 0; n < 4; n++) upk2(lo[n], hi[n], acc2[mp][n]);
        int r0 = brow + m0 + 2 * mp;
        float4 v0, v1;
        v0.x = lo[0] + bv.x; v0.y = lo[1] + bv.y; v0.z = lo[2] + bv.z; v0.w = lo[3] + bv.w;
        v1.x = hi[0] + bv.x; v1.y = hi[1] + bv.y; v1.z = hi[2] + bv.z; v1.w = hi[3] + bv.w;
        *(float4*)(g_QK + (size_t)r0 * 512 + bcol + n0) = v0;
        *(float4*)(g_QK + (size_t)(r0 + 1) * 512 + bcol + n0) = v1;
    }
}

// ---------------------------------------------------------------------------
// Attention: phase A stages K[160][256]+Q[32][256]; phase B computes all
// 4x32x160 scores as a register-tiled GEMM (2 nodes x 5 rows per thread,
// K rows reused across nodes in registers); phase C does the proven
// warp-per-node softmax (unmasked zero-padding, as the reference) +
// exact top-32 + parallel scatter of 1.0f.
// ---------------------------------------------------------------------------
__global__ __launch_bounds__(ATHR) void attn_topk_kernel(float* __restrict__ out)
{
    extern __shared__ float smem[];
    float* Ksm = smem;                        // [MAXR][KSTRB]
    float* Qsm = smem + MAXR * KSTRB;         // [NPB][QROW]
    float* Ssm = smem;                        // aliases Ksm after phase B: [4*NPB][SROW]

    const int tid  = threadIdx.x;
    const int i0   = blockIdx.x * NPB;
    const int s0   = i0 & ~(SEG - 1);
    const int e0   = s0 + SEG;
    const int w_lo = max(s0, i0 - HALF);
    const int w_hi = min(e0, i0 + (NPB - 1) + HALF);
    const int rows = w_hi - w_lo;             // <= 159

    // ---- phase A: stage K rows [w_lo, w_hi) and Q rows i0..i0+31
    for (int idx = tid; idx < rows * 64; idx += ATHR) {
        int r = idx >> 6;
        int c = (idx & 63) << 2;
        *(float4*)(Ksm + r * KSTRB + c) =
            *(const float4*)(g_QK + (size_t)(w_lo + r) * 512 + 256 + c);
    }
    for (int idx = tid; idx < NPB * 64; idx += ATHR) {
        int r = idx >> 6;
        int c = (idx & 63) << 2;
        *(float4*)(Qsm + r * QROW + c) =
            *(const float4*)(g_QK + (size_t)(i0 + r) * 512 + c);
    }
    __syncthreads();

    // ---- phase B: score GEMM. thread -> (head-pair hp, node-pair it, row-5 jt)
    const int jt = tid & 31;                  // rows jt*5 .. jt*5+4
    const int it = (tid >> 5) & 15;           // nodes it*2, it*2+1
    const int hp = tid >> 9;                  // heads hp*2+{0,1}

    float sc[2][10];
#pragma unroll
    for (int hh = 0; hh < 2; hh++) {
        const int h = hp * 2 + hh;
        unsigned long long acc[2][5];
#pragma unroll
        for (int a = 0; a < 2; a++)
#pragma unroll
            for (int r = 0; r < 5; r++) acc[a][r] = 0ULL;

        const float* kb = Ksm + (jt * 5) * KSTRB + h * HD;
        const float* qb = Qsm + (it * 2) * QROW + h * HD;
#pragma unroll
        for (int d = 0; d < 16; d++) {
            ulonglong2 qa = *(const ulonglong2*)(qb + d * 4);          // node A (bcast)
            ulonglong2 qn = *(const ulonglong2*)(qb + QROW + d * 4);   // node B (bcast)
#pragma unroll
            for (int r = 0; r < 5; r++) {
                ulonglong2 kv = *(const ulonglong2*)(kb + r * KSTRB + d * 4);
                acc[0][r] = fma2(kv.x, qa.x, acc[0][r]);
                acc[0][r] = fma2(kv.y, qa.y, acc[0][r]);
                acc[1][r] = fma2(kv.x, qn.x, acc[1][r]);
                acc[1][r] = fma2(kv.y, qn.y, acc[1][r]);
            }
        }
#pragma unroll
        for (int a = 0; a < 2; a++)
#pragma unroll
            for (int r = 0; r < 5; r++) {
                float lo, hi;
                upk2(lo, hi, acc[a][r]);
                sc[hh][a * 5 + r] = (lo + hi) * 0.25f;   // /sqrt(64)/tau
            }
    }
    __syncthreads();   // all K reads done; Ksm region now reusable

    // write scores: Ssm[(h*32 + node)][jw], jw = jt*5 + r
#pragma unroll
    for (int hh = 0; hh < 2; hh++) {
        const int h = hp * 2 + hh;
#pragma unroll
        for (int a = 0; a < 2; a++) {
            float* dst = Ssm + (size_t)(h * NPB + it * 2 + a) * SROW + jt * 5;
#pragma unroll
            for (int r = 0; r < 5; r++) dst[r] = sc[hh][a * 5 + r];
        }
    }
    __syncthreads();

    // ---- phase C: warp-per-node softmax + exact top-32
    const int w    = tid >> 5;
    const int lane = tid & 31;
    const int i    = i0 + w;
    const int start = max(s0, i - HALF);
    const int end   = min(e0, i + HALF);      // exclusive; valid count in [65,128]
    const int off   = start - w_lo;

    bool val[4];
#pragma unroll
    for (int q = 0; q < 4; q++)
        val[q] = (start + q * 32 + lane) < end;

    float attn[4] = {0.f, 0.f, 0.f, 0.f};
#pragma unroll
    for (int h = 0; h < NHEAD; h++) {
        const float* srow = Ssm + (size_t)(h * NPB + w) * SROW + off;
        float e[4];
        float s = 0.f;
#pragma unroll
        for (int q = 0; q < 4; q++) {
            float a = val[q] ? srow[q * 32 + lane] : 0.f;  // pad slots -> score 0
            e[q] = __expf(a);                              // pad -> exactly 1
            s += e[q];
        }
#pragma unroll
        for (int o = 16; o > 0; o >>= 1)
            s += __shfl_xor_sync(0xffffffffu, s, o);
        float rs = __fdividef(1.f, s);
#pragma unroll
        for (int q = 0; q < 4; q++) attn[q] += e[q] * rs;
    }

    // keys: valid slots have attn > 0, so raw float bits are order-isomorphic
    // as u32; invalid slots get key 0. attn*0.25 <= 1.0 -> bits 31,30 are 0.
    unsigned u[4];
#pragma unroll
    for (int q = 0; q < 4; q++)
        u[q] = val[q] ? __float_as_uint(attn[q] * 0.25f) : 0u;

    // radix descent: find T = 32nd-largest key (exact)
    unsigned T = 0;
#pragma unroll 1
    for (int bit = 29; bit >= 0; --bit) {
        unsigned cand = T | (1u << bit);
        int c = (u[0] >= cand) + (u[1] >= cand) + (u[2] >= cand) + (u[3] >= cand);
        c = __reduce_add_sync(0xffffffffu, c);
        if (c >= TOPK) T = cand;
    }

    // select: everything > T, plus ties == T filled in ascending slot order
    // (matches jax.lax.top_k's smaller-index-first tie rule)
    int gt = (u[0] > T) + (u[1] > T) + (u[2] > T) + (u[3] > T);
    int rem = TOPK - __reduce_add_sync(0xffffffffu, gt);

    const size_t rowbase = (size_t)i * NN + start;
#pragma unroll
    for (int q = 0; q < 4; q++) {
        bool eq = (u[q] == T);
        unsigned meq = __ballot_sync(0xffffffffu, eq);
        int before = __popc(meq & ((1u << lane) - 1u));
        bool sel = (u[q] > T) || (eq && before < rem);
        if (sel) out[rowbase + q * 32 + lane] = 1.0f;
        int tk = __popc(meq);
        rem -= (tk < rem) ? tk : rem;
    }
}

// ---------------------------------------------------------------------------
extern "C" void kernel_launch(void* const* d_in, const int* in_sizes, int n_in,
                              void* d_out, int out_size)
{
    (void)in_sizes; (void)n_in; (void)out_size;
    const float* X  = (const float*)d_in[0];
    const float* Wq = (const float*)d_in[1];
    const float* bq = (const float*)d_in[2];
    const float* Wk = (const float*)d_in[3];
    const float* bk = (const float*)d_in[4];
    float* out = (float*)d_out;

    // 1) Q||K projection GEMM + zero-fill of the 4096x4096 output
    dim3 ggrid(512 / GBN, NN / GBM);          // (8, 64) = 512 blocks
    gemm_qk_kernel<<<ggrid, GTHR>>>(X, Wq, bq, Wk, bk, (float4*)out);

    // 2) attention score GEMM + softmax + exact top-32 scatter
    const int smem_bytes = (MAXR * KSTRB + NPB * QROW) * (int)sizeof(float);
    cudaFuncSetAttribute(attn_topk_kernel,
                         cudaFuncAttributeMaxDynamicSharedMemorySize, smem_bytes);
    attn_topk_kernel<<<NN / NPB, ATHR, smem_bytes>>>(out);
}

// round 8
// speedup vs baseline: 1.4868x; 1.4868x over previous
#include <cuda_runtime.h>
#include <math.h>

// Problem constants (fixed by setup_inputs)
#define NN    4096
#define INF_  256
#define SEG   512
#define HALF  64
#define WIN   128
#define NHEAD 4
#define HD    64
#define TOPK  32

// attention kernel tiling
#define NPB   32             // nodes per block
#define ATHR  1024           // attention threads per block (32 warps)
#define MAXR  160            // union window rows: (NPB-1)+128 = 159, pad to 160
#define KSTRB 276            // K smem row stride; 5-row lane stride -> conflict-free LDS.128
#define QROW  256
#define SROW  164            // score row stride

// GEMM tiling
#define GBM 64
#define GBN 64
#define GBK 16
#define GTHR 128
#define ASTR 68              // padded smem stride (272B rows, 16B aligned)
#define NTILE (INF_ / GBK)   // 16 k-tiles

// scratch: Q||K projections, [4096][512]  (cols 0..255 = Q, 256..511 = K)
__device__ float g_QK[(size_t)NN * 512];

// ---------------------------------------------------------------------------
// packed fp32x2 helpers (sm_100+: fma.rn.f32x2 — 2 IEEE fp32 FMAs per issue)
// ---------------------------------------------------------------------------
__device__ __forceinline__ unsigned long long pk2(float x, float y) {
    unsigned long long r;
    asm("mov.b64 %0, {%1, %2};" : "=l"(r) : "f"(x), "f"(y));
    return r;
}
__device__ __forceinline__ void upk2(float& x, float& y, unsigned long long r) {
    asm("mov.b64 {%0, %1}, %2;" : "=f"(x), "=f"(y) : "l"(r));
}
__device__ __forceinline__ unsigned long long fma2(unsigned long long a,
                                                   unsigned long long b,
                                                   unsigned long long c) {
    unsigned long long d;
    asm("fma.rn.f32x2 %0, %1, %2, %3;" : "=l"(d) : "l"(a), "l"(b), "l"(c));
    return d;
}

// ---------------------------------------------------------------------------
// fused Q||K projection GEMM:  C[4096,512] = X[4096,256] @ [Wq|Wk] + [bq|bk]
// BM=64, BN=64, BK=16, 128 threads, 8x4 per thread (round-6 inner loop),
// DOUBLE-BUFFERED smem tiles: next tile's LDGs issue before the current
// tile's math, one __syncthreads per k-tile. Each block also zero-fills
// 128 KB (8 rows) of the output matrix.
// ---------------------------------------------------------------------------
__global__ __launch_bounds__(GTHR) void gemm_qk_kernel(
    const float* __restrict__ X,
    const float* __restrict__ Wq, const float* __restrict__ bq,
    const float* __restrict__ Wk, const float* __restrict__ bk,
    float4* __restrict__ out4)
{
    __shared__ float As[2][GBK][ASTR];   // transposed A tile [k][m]
    __shared__ float Bs[2][GBK][ASTR];   // B tile [k][n]

    const int tid = threadIdx.x;

    // ---- zero-fill slice of the output: block zb covers 8 rows (128 KB)
    {
        const int zb = blockIdx.y * gridDim.x + blockIdx.x;   // 0..511
        float4* zdst = out4 + (size_t)zb * (8 * NN / 4);
        const float4 z = make_float4(0.f, 0.f, 0.f, 0.f);
#pragma unroll
        for (int t = 0; t < (8 * NN / 4) / GTHR; t++)
            zdst[t * GTHR + tid] = z;
    }

    const int brow = blockIdx.y * GBM;
    const int bcol = blockIdx.x * GBN;

    // each block lies entirely in the Q half (bcol<256) or K half
    const float* W    = (bcol < 256) ? Wq : Wk;
    const float* bias = (bcol < 256) ? bq : bk;
    const int wcol = bcol & 255;

    const int tx = tid & 15;          // n0 = tx*4
    const int ty = tid >> 4;          // m0 = ty*8
    const int m0 = ty * 8;
    const int n0 = tx * 4;

    // per-thread gmem load coordinates (2 float4 each for A and B per tile)
    const int ar0 = tid >> 1;                 // A rows (tid, tid+128)/... f>>2 layout below
    (void)ar0;

    // prefetch registers
    float4 xa[2], xb[2];

    // ---- load tile 0 into registers
#pragma unroll
    for (int t = 0; t < 2; t++) {
        int f = tid + t * GTHR;
        int r = f >> 2;
        int c = (f & 3) << 2;
        xa[t] = *(const float4*)(X + (size_t)(brow + r) * INF_ + c);
        int rb = f >> 4;
        int cb = (f & 15) << 2;
        xb[t] = *(const float4*)(W + (size_t)rb * 256 + wcol + cb);
    }
    // store tile 0 to buffer 0
#pragma unroll
    for (int t = 0; t < 2; t++) {
        int f = tid + t * GTHR;
        int r = f >> 2;
        int c = (f & 3) << 2;
        As[0][c + 0][r] = xa[t].x;
        As[0][c + 1][r] = xa[t].y;
        As[0][c + 2][r] = xa[t].z;
        As[0][c + 3][r] = xa[t].w;
        int rb = f >> 4;
        int cb = (f & 15) << 2;
        *(float4*)&Bs[0][rb][cb] = xb[t];
    }
    __syncthreads();

    unsigned long long acc2[4][4];    // [m-pair][n]
#pragma unroll
    for (int a = 0; a < 4; a++)
#pragma unroll
        for (int b = 0; b < 4; b++) acc2[a][b] = 0ULL;

#pragma unroll
    for (int it = 0; it < NTILE; it++) {
        const int cur = it & 1;

        // issue next tile's LDGs early (latency hidden by the math below)
        if (it + 1 < NTILE) {
            const int k0 = (it + 1) * GBK;
#pragma unroll
            for (int t = 0; t < 2; t++) {
                int f = tid + t * GTHR;
                int r = f >> 2;
                int c = (f & 3) << 2;
                xa[t] = *(const float4*)(X + (size_t)(brow + r) * INF_ + k0 + c);
                int rb = f >> 4;
                int cb = (f & 15) << 2;
                xb[t] = *(const float4*)(W + (size_t)(k0 + rb) * 256 + wcol + cb);
            }
        }

        // math on current buffer (round-6 inner loop, measured-good)
#pragma unroll
        for (int k = 0; k < GBK; k++) {
            float a[8], b[4];
            *(float4*)&a[0] = *(float4*)&As[cur][k][m0];
            *(float4*)&a[4] = *(float4*)&As[cur][k][m0 + 4];
            *(float4*)&b[0] = *(float4*)&Bs[cur][k][n0];
            unsigned long long a2[4];
            a2[0] = pk2(a[0], a[1]);
            a2[1] = pk2(a[2], a[3]);
            a2[2] = pk2(a[4], a[5]);
            a2[3] = pk2(a[6], a[7]);
            unsigned long long bd[4];
            bd[0] = pk2(b[0], b[0]);
            bd[1] = pk2(b[1], b[1]);
            bd[2] = pk2(b[2], b[2]);
            bd[3] = pk2(b[3], b[3]);
#pragma unroll
            for (int mp = 0; mp < 4; mp++)
#pragma unroll
                for (int n = 0; n < 4; n++)
                    acc2[mp][n] = fma2(a2[mp], bd[n], acc2[mp][n]);
        }

        // stage next tile into the other buffer (safe: last reads of that
        // buffer were ordered by the previous __syncthreads)
        if (it + 1 < NTILE) {
            const int nxt = cur ^ 1;
#pragma unroll
            for (int t = 0; t < 2; t++) {
                int f = tid + t * GTHR;
                int r = f >> 2;
                int c = (f & 3) << 2;
                As[nxt][c + 0][r] = xa[t].x;
                As[nxt][c + 1][r] = xa[t].y;
                As[nxt][c + 2][r] = xa[t].z;
                As[nxt][c + 3][r] = xa[t].w;
                int rb = f >> 4;
                int cb = (f & 15) << 2;
                *(float4*)&Bs[nxt][rb][cb] = xb[t];
            }
            __syncthreads();
        }
    }

    // epilogue: unpack, +bias, store two rows per m-pair
    float4 bv = *(const float4*)(bias + wcol + n0);
#pragma unroll
    for (int mp = 0; mp < 4; mp++) {
        float lo[4], hi[4];
#pragma unroll
        for (int n = 0; n < 4; n++) upk2(lo[n], hi[n], acc2[mp][n]);
        int r0 = brow + m0 + 2 * mp;
        float4 v0, v1;
        v0.x = lo[0] + bv.x; v0.y = lo[1] + bv.y; v0.z = lo[2] + bv.z; v0.w = lo[3] + bv.w;
        v1.x = hi[0] + bv.x; v1.y = hi[1] + bv.y; v1.z = hi[2] + bv.z; v1.w = hi[3] + bv.w;
        *(float4*)(g_QK + (size_t)r0 * 512 + bcol + n0) = v0;
        *(float4*)(g_QK + (size_t)(r0 + 1) * 512 + bcol + n0) = v1;
    }
}

// ---------------------------------------------------------------------------
// Attention (unchanged from round 7 — measured 26.8us, rel_err 0):
// phase A stages K[160][256]+Q[32][256]; phase B computes all 4x32x160
// scores as a register-tiled GEMM (2 nodes x 5 rows per thread); phase C
// does warp-per-node softmax (unmasked zero-padding, as the reference) +
// exact top-32 + parallel scatter of 1.0f.
// ---------------------------------------------------------------------------
__global__ __launch_bounds__(ATHR) void attn_topk_kernel(float* __restrict__ out)
{
    extern __shared__ float smem[];
    float* Ksm = smem;                        // [MAXR][KSTRB]
    float* Qsm = smem + MAXR * KSTRB;         // [NPB][QROW]
    float* Ssm = smem;                        // aliases Ksm after phase B: [4*NPB][SROW]

    const int tid  = threadIdx.x;
    const int i0   = blockIdx.x * NPB;
    const int s0   = i0 & ~(SEG - 1);
    const int e0   = s0 + SEG;
    const int w_lo = max(s0, i0 - HALF);
    const int w_hi = min(e0, i0 + (NPB - 1) + HALF);
    const int rows = w_hi - w_lo;             // <= 159

    // ---- phase A: stage K rows [w_lo, w_hi) and Q rows i0..i0+31
    for (int idx = tid; idx < rows * 64; idx += ATHR) {
        int r = idx >> 6;
        int c = (idx & 63) << 2;
        *(float4*)(Ksm + r * KSTRB + c) =
            *(const float4*)(g_QK + (size_t)(w_lo + r) * 512 + 256 + c);
    }
    for (int idx = tid; idx < NPB * 64; idx += ATHR) {
        int r = idx >> 6;
        int c = (idx & 63) << 2;
        *(float4*)(Qsm + r * QROW + c) =
            *(const float4*)(g_QK + (size_t)(i0 + r) * 512 + c);
    }
    __syncthreads();

    // ---- phase B: score GEMM. thread -> (head-pair hp, node-pair it, row-5 jt)
    const int jt = tid & 31;                  // rows jt*5 .. jt*5+4
    const int it = (tid >> 5) & 15;           // nodes it*2, it*2+1
    const int hp = tid >> 9;                  // heads hp*2+{0,1}

    float sc[2][10];
#pragma unroll
    for (int hh = 0; hh < 2; hh++) {
        const int h = hp * 2 + hh;
        unsigned long long acc[2][5];
#pragma unroll
        for (int a = 0; a < 2; a++)
#pragma unroll
            for (int r = 0; r < 5; r++) acc[a][r] = 0ULL;

        const float* kb = Ksm + (jt * 5) * KSTRB + h * HD;
        const float* qb = Qsm + (it * 2) * QROW + h * HD;
#pragma unroll
        for (int d = 0; d < 16; d++) {
            ulonglong2 qa = *(const ulonglong2*)(qb + d * 4);          // node A (bcast)
            ulonglong2 qn = *(const ulonglong2*)(qb + QROW + d * 4);   // node B (bcast)
#pragma unroll
            for (int r = 0; r < 5; r++) {
                ulonglong2 kv = *(const ulonglong2*)(kb + r * KSTRB + d * 4);
                acc[0][r] = fma2(kv.x, qa.x, acc[0][r]);
                acc[0][r] = fma2(kv.y, qa.y, acc[0][r]);
                acc[1][r] = fma2(kv.x, qn.x, acc[1][r]);
                acc[1][r] = fma2(kv.y, qn.y, acc[1][r]);
            }
        }
#pragma unroll
        for (int a = 0; a < 2; a++)
#pragma unroll
            for (int r = 0; r < 5; r++) {
                float lo, hi;
                upk2(lo, hi, acc[a][r]);
                sc[hh][a * 5 + r] = (lo + hi) * 0.25f;   // /sqrt(64)/tau
            }
    }
    __syncthreads();   // all K reads done; Ksm region now reusable

    // write scores: Ssm[(h*32 + node)][jw], jw = jt*5 + r
#pragma unroll
    for (int hh = 0; hh < 2; hh++) {
        const int h = hp * 2 + hh;
#pragma unroll
        for (int a = 0; a < 2; a++) {
            float* dst = Ssm + (size_t)(h * NPB + it * 2 + a) * SROW + jt * 5;
#pragma unroll
            for (int r = 0; r < 5; r++) dst[r] = sc[hh][a * 5 + r];
        }
    }
    __syncthreads();

    // ---- phase C: warp-per-node softmax + exact top-32
    const int w    = tid >> 5;
    const int lane = tid & 31;
    const int i    = i0 + w;
    const int start = max(s0, i - HALF);
    const int end   = min(e0, i + HALF);      // exclusive; valid count in [65,128]
    const int off   = start - w_lo;

    bool val[4];
#pragma unroll
    for (int q = 0; q < 4; q++)
        val[q] = (start + q * 32 + lane) < end;

    float attn[4] = {0.f, 0.f, 0.f, 0.f};
#pragma unroll
    for (int h = 0; h < NHEAD; h++) {
        const float* srow = Ssm + (size_t)(h * NPB + w) * SROW + off;
        float e[4];
        float s = 0.f;
#pragma unroll
        for (int q = 0; q < 4; q++) {
            float a = val[q] ? srow[q * 32 + lane] : 0.f;  // pad slots -> score 0
            e[q] = __expf(a);                              // pad -> exactly 1
            s += e[q];
        }
#pragma unroll
        for (int o = 16; o > 0; o >>= 1)
            s += __shfl_xor_sync(0xffffffffu, s, o);
        float rs = __fdividef(1.f, s);
#pragma unroll
        for (int q = 0; q < 4; q++) attn[q] += e[q] * rs;
    }

    // keys: valid slots have attn > 0, so raw float bits are order-isomorphic
    // as u32; invalid slots get key 0. attn*0.25 <= 1.0 -> bits 31,30 are 0.
    unsigned u[4];
#pragma unroll
    for (int q = 0; q < 4; q++)
        u[q] = val[q] ? __float_as_uint(attn[q] * 0.25f) : 0u;

    // radix descent: find T = 32nd-largest key (exact)
    unsigned T = 0;
#pragma unroll 1
    for (int bit = 29; bit >= 0; --bit) {
        unsigned cand = T | (1u << bit);
        int c = (u[0] >= cand) + (u[1] >= cand) + (u[2] >= cand) + (u[3] >= cand);
        c = __reduce_add_sync(0xffffffffu, c);
        if (c >= TOPK) T = cand;
    }

    // select: everything > T, plus ties == T filled in ascending slot order
    // (matches jax.lax.top_k's smaller-index-first tie rule)
    int gt = (u[0] > T) + (u[1] > T) + (u[2] > T) + (u[3] > T);
    int rem = TOPK - __reduce_add_sync(0xffffffffu, gt);

    const size_t rowbase = (size_t)i * NN + start;
#pragma unroll
    for (int q = 0; q < 4; q++) {
        bool eq = (u[q] == T);
        unsigned meq = __ballot_sync(0xffffffffu, eq);
        int before = __popc(meq & ((1u << lane) - 1u));
        bool sel = (u[q] > T) || (eq && before < rem);
        if (sel) out[rowbase + q * 32 + lane] = 1.0f;
        int tk = __popc(meq);
        rem -= (tk < rem) ? tk : rem;
    }
}

// ---------------------------------------------------------------------------
extern "C" void kernel_launch(void* const* d_in, const int* in_sizes, int n_in,
                              void* d_out, int out_size)
{
    (void)in_sizes; (void)n_in; (void)out_size;
    const float* X  = (const float*)d_in[0];
    const float* Wq = (const float*)d_in[1];
    const float* bq = (const float*)d_in[2];
    const float* Wk = (const float*)d_in[3];
    const float* bk = (const float*)d_in[4];
    float* out = (float*)d_out;

    // 1) Q||K projection GEMM + zero-fill of the 4096x4096 output
    dim3 ggrid(512 / GBN, NN / GBM);          // (8, 64) = 512 blocks
    gemm_qk_kernel<<<ggrid, GTHR>>>(X, Wq, bq, Wk, bk, (float4*)out);

    // 2) attention score GEMM + softmax + exact top-32 scatter
    const int smem_bytes = (MAXR * KSTRB + NPB * QROW) * (int)sizeof(float);
    cudaFuncSetAttribute(attn_topk_kernel,
                         cudaFuncAttributeMaxDynamicSharedMemorySize, smem_bytes);
    attn_topk_kernel<<<NN / NPB, ATHR, smem_bytes>>>(out);
}

// round 13
// speedup vs baseline: 1.8051x; 1.2141x over previous
#include <cuda_runtime.h>
#include <math.h>

// Problem constants (fixed by setup_inputs)
#define NN    4096
#define INF_  256
#define SEG   512
#define HALF  64
#define WIN   128
#define NHEAD 4
#define HD    64
#define TOPK  32

// attention kernel tiling
#define NPB   32             // nodes per block
#define ATHR  1024           // attention threads per block (32 warps)
#define MAXR  160            // union window rows: (NPB-1)+128 = 159, pad to 160
#define KSTRB 282            // K smem row stride; lane stride 5*282 -> conflict-free LDS.64
                             // NOTE: 282*4 B is only 8B-aligned -> K staging uses STS.64
#define QROW  256
#define SROW  164            // score row stride

// GEMM tiling
#define GBM 64
#define GBN 64
#define GBK 16
#define GTHR 128
#define ASTR 68              // padded smem stride (272B rows, 16B aligned)
#define NTILE (INF_ / GBK)   // 16 k-tiles

// scratch: Q||K projections, [4096][512]  (cols 0..255 = Q, 256..511 = K)
__device__ float g_QK[(size_t)NN * 512];

// ---------------------------------------------------------------------------
// packed fp32x2 helpers (sm_100+: fma.rn.f32x2 — 2 IEEE fp32 FMAs per issue)
// ---------------------------------------------------------------------------
__device__ __forceinline__ unsigned long long pk2(float x, float y) {
    unsigned long long r;
    asm("mov.b64 %0, {%1, %2};" : "=l"(r) : "f"(x), "f"(y));
    return r;
}
__device__ __forceinline__ void upk2(float& x, float& y, unsigned long long r) {
    asm("mov.b64 {%0, %1}, %2;" : "=f"(x), "=f"(y) : "l"(r));
}
__device__ __forceinline__ unsigned long long fma2(unsigned long long a,
                                                   unsigned long long b,
                                                   unsigned long long c) {
    unsigned long long d;
    asm("fma.rn.f32x2 %0, %1, %2, %3;" : "=l"(d) : "l"(a), "l"(b), "l"(c));
    return d;
}

// ---------------------------------------------------------------------------
// fused Q||K projection GEMM:  C[4096,512] = X[4096,256] @ [Wq|Wk] + [bq|bk]
// BM=64, BN=64, BK=16, 128 threads, 8x4 per thread, double-buffered smem.
// The 128 KB zero-fill slice of the output is INTERLEAVED into the k-tile
// loop (1 float4 store per thread per iteration) so the L2 write drain
// overlaps the fma2-bound mainloop instead of serializing in a prologue.
// ---------------------------------------------------------------------------
__global__ __launch_bounds__(GTHR) void gemm_qk_kernel(
    const float* __restrict__ X,
    const float* __restrict__ Wq, const float* __restrict__ bq,
    const float* __restrict__ Wk, const float* __restrict__ bk,
    float4* __restrict__ out4)
{
    __shared__ float As[2][GBK][ASTR];   // transposed A tile [k][m]
    __shared__ float Bs[2][GBK][ASTR];   // B tile [k][n]

    const int tid = threadIdx.x;

    const int brow = blockIdx.y * GBM;
    const int bcol = blockIdx.x * GBN;

    // each block lies entirely in the Q half (bcol<256) or K half
    const float* W    = (bcol < 256) ? Wq : Wk;
    const float* bias = (bcol < 256) ? bq : bk;
    const int wcol = bcol & 255;

    // zero-fill slice: block zb covers 8 rows (2048 float4) of the output
    const int zb = blockIdx.y * gridDim.x + blockIdx.x;   // 0..511
    float4* zdst = out4 + (size_t)zb * (8 * NN / 4);
    const float4 zv = make_float4(0.f, 0.f, 0.f, 0.f);

    const int tx = tid & 15;          // n0 = tx*4
    const int ty = tid >> 4;          // m0 = ty*8
    const int m0 = ty * 8;
    const int n0 = tx * 4;

    // prefetch registers
    float4 xa[2], xb[2];

    // ---- load tile 0 into registers (LDGs first, in flight ASAP)
#pragma unroll
    for (int t = 0; t < 2; t++) {
        int f = tid + t * GTHR;
        int r = f >> 2;
        int c = (f & 3) << 2;
        xa[t] = *(const float4*)(X + (size_t)(brow + r) * INF_ + c);
        int rb = f >> 4;
        int cb = (f & 15) << 2;
        xb[t] = *(const float4*)(W + (size_t)rb * 256 + wcol + cb);
    }
    // store tile 0 to buffer 0
#pragma unroll
    for (int t = 0; t < 2; t++) {
        int f = tid + t * GTHR;
        int r = f >> 2;
        int c = (f & 3) << 2;
        As[0][c + 0][r] = xa[t].x;
        As[0][c + 1][r] = xa[t].y;
        As[0][c + 2][r] = xa[t].z;
        As[0][c + 3][r] = xa[t].w;
        int rb = f >> 4;
        int cb = (f & 15) << 2;
        *(float4*)&Bs[0][rb][cb] = xb[t];
    }
    __syncthreads();

    unsigned long long acc2[4][4];    // [m-pair][n]
#pragma unroll
    for (int a = 0; a < 4; a++)
#pragma unroll
        for (int b = 0; b < 4; b++) acc2[a][b] = 0ULL;

#pragma unroll
    for (int it = 0; it < NTILE; it++) {
        const int cur = it & 1;

        // issue next tile's LDGs early (latency hidden by the math below)
        if (it + 1 < NTILE) {
            const int k0 = (it + 1) * GBK;
#pragma unroll
            for (int t = 0; t < 2; t++) {
                int f = tid + t * GTHR;
                int r = f >> 2;
                int c = (f & 3) << 2;
                xa[t] = *(const float4*)(X + (size_t)(brow + r) * INF_ + k0 + c);
                int rb = f >> 4;
                int cb = (f & 15) << 2;
                xb[t] = *(const float4*)(W + (size_t)(k0 + rb) * 256 + wcol + cb);
            }
        }

        // one slice of the output zero-fill per iteration (overlaps compute)
        zdst[it * GTHR + tid] = zv;

        // math on current buffer
#pragma unroll
        for (int k = 0; k < GBK; k++) {
            float a[8], b[4];
            *(float4*)&a[0] = *(float4*)&As[cur][k][m0];
            *(float4*)&a[4] = *(float4*)&As[cur][k][m0 + 4];
            *(float4*)&b[0] = *(float4*)&Bs[cur][k][n0];
            unsigned long long a2[4];
            a2[0] = pk2(a[0], a[1]);
            a2[1] = pk2(a[2], a[3]);
            a2[2] = pk2(a[4], a[5]);
            a2[3] = pk2(a[6], a[7]);
            unsigned long long bd[4];
            bd[0] = pk2(b[0], b[0]);
            bd[1] = pk2(b[1], b[1]);
            bd[2] = pk2(b[2], b[2]);
            bd[3] = pk2(b[3], b[3]);
#pragma unroll
            for (int mp = 0; mp < 4; mp++)
#pragma unroll
                for (int n = 0; n < 4; n++)
                    acc2[mp][n] = fma2(a2[mp], bd[n], acc2[mp][n]);
        }

        // stage next tile into the other buffer (safe: last reads of that
        // buffer were ordered by the previous __syncthreads)
        if (it + 1 < NTILE) {
            const int nxt = cur ^ 1;
#pragma unroll
            for (int t = 0; t < 2; t++) {
                int f = tid + t * GTHR;
                int r = f >> 2;
                int c = (f & 3) << 2;
                As[nxt][c + 0][r] = xa[t].x;
                As[nxt][c + 1][r] = xa[t].y;
                As[nxt][c + 2][r] = xa[t].z;
                As[nxt][c + 3][r] = xa[t].w;
                int rb = f >> 4;
                int cb = (f & 15) << 2;
                *(float4*)&Bs[nxt][rb][cb] = xb[t];
            }
            __syncthreads();
        }
    }

    // epilogue: unpack, +bias, store two rows per m-pair
    float4 bv = *(const float4*)(bias + wcol + n0);
#pragma unroll
    for (int mp = 0; mp < 4; mp++) {
        float lo[4], hi[4];
#pragma unroll
        for (int n = 0; n < 4; n++) upk2(lo[n], hi[n], acc2[mp][n]);
        int r0 = brow + m0 + 2 * mp;
        float4 v0, v1;
        v0.x = lo[0] + bv.x; v0.y = lo[1] + bv.y; v0.z = lo[2] + bv.z; v0.w = lo[3] + bv.w;
        v1.x = hi[0] + bv.x; v1.y = hi[1] + bv.y; v1.z = hi[2] + bv.z; v1.w = hi[3] + bv.w;
        *(float4*)(g_QK + (size_t)r0 * 512 + bcol + n0) = v0;
        *(float4*)(g_QK + (size_t)(r0 + 1) * 512 + bcol + n0) = v1;
    }
}

// ---------------------------------------------------------------------------
// Attention: phase A stages K[160][282]+Q[32][256]; phase B computes all
// 4x32x160 scores as a register-tiled GEMM with thread tile = 1 head x
// 4 nodes x 5 rows (K rows reused 4x in registers, LDS.64 d-chunks);
// phase C does warp-per-node softmax (unmasked zero-padding, as the
// reference) + exact top-32 + parallel scatter of 1.0f.
// K staging uses 8-byte stores because KSTRB rows are only 8B-aligned.
// ---------------------------------------------------------------------------
__global__ __launch_bounds__(ATHR) void attn_topk_kernel(float* __restrict__ out)
{
    extern __shared__ float smem[];
    float* Ksm = smem;                        // [MAXR][KSTRB]
    float* Qsm = smem + MAXR * KSTRB;         // [NPB][QROW] (160*282 floats = 16B-aligned)
    float* Ssm = smem;                        // aliases Ksm after phase B: [4*NPB][SROW]

    const int tid  = threadIdx.x;
    const int i0   = blockIdx.x * NPB;
    const int s0   = i0 & ~(SEG - 1);
    const int e0   = s0 + SEG;
    const int w_lo = max(s0, i0 - HALF);
    const int w_hi = min(e0, i0 + (NPB - 1) + HALF);
    const int rows = w_hi - w_lo;             // <= 159

    // ---- phase A: stage K rows [w_lo, w_hi) (STS.64 x2 — rows 8B-aligned)
    for (int idx = tid; idx < rows * 64; idx += ATHR) {
        int r = idx >> 6;
        int c = (idx & 63) << 2;
        float4 v = *(const float4*)(g_QK + (size_t)(w_lo + r) * 512 + 256 + c);
        float* dst = Ksm + r * KSTRB + c;
        *(float2*)(dst)     = make_float2(v.x, v.y);
        *(float2*)(dst + 2) = make_float2(v.z, v.w);
    }
    // stage Q rows i0..i0+31 (QROW=256 -> rows 16B-aligned, float4 OK)
    for (int idx = tid; idx < NPB * 64; idx += ATHR) {
        int r = idx >> 6;
        int c = (idx & 63) << 2;
        *(float4*)(Qsm + r * QROW + c) =
            *(const float4*)(g_QK + (size_t)(i0 + r) * 512 + c);
    }
    __syncthreads();

    // ---- phase B: score GEMM. thread -> (head h, node-quad ng, row-5 rg)
    const int rg = tid & 31;                  // rows rg*5 .. rg*5+4
    const int ng = (tid >> 5) & 7;            // nodes ng*4 .. ng*4+3
    const int h  = tid >> 8;                  // head

    const float* kb = Ksm + (rg * 5) * KSTRB + h * HD;
    const float* qb = Qsm + (ng * 4) * QROW + h * HD;

    unsigned long long acc[4][5];
#pragma unroll
    for (int a = 0; a < 4; a++)
#pragma unroll
        for (int r = 0; r < 5; r++) acc[a][r] = 0ULL;

#pragma unroll
    for (int d2 = 0; d2 < 32; d2++) {         // 2 floats per step
        unsigned long long qd[4];
#pragma unroll
        for (int a = 0; a < 4; a++)           // warp-broadcast LDS.64
            qd[a] = *(const unsigned long long*)(qb + a * QROW + d2 * 2);
#pragma unroll
        for (int r = 0; r < 5; r++) {
            unsigned long long kv =
                *(const unsigned long long*)(kb + r * KSTRB + d2 * 2);
#pragma unroll
            for (int a = 0; a < 4; a++)
                acc[a][r] = fma2(kv, qd[a], acc[a][r]);
        }
    }

    float sc[4][5];
#pragma unroll
    for (int a = 0; a < 4; a++)
#pragma unroll
        for (int r = 0; r < 5; r++) {
            float lo, hi;
            upk2(lo, hi, acc[a][r]);
            sc[a][r] = (lo + hi) * 0.25f;     // /sqrt(64)/tau
        }
    __syncthreads();   // all K reads done; Ksm region now reusable

    // write scores: Ssm[(h*32 + node)][row]
#pragma unroll
    for (int a = 0; a < 4; a++) {
        float* dst = Ssm + (size_t)(h * NPB + ng * 4 + a) * SROW + rg * 5;
#pragma unroll
        for (int r = 0; r < 5; r++) dst[r] = sc[a][r];
    }
    __syncthreads();

    // ---- phase C: warp-per-node softmax + exact top-32
    const int w    = tid >> 5;
    const int lane = tid & 31;
    const int i    = i0 + w;
    const int start = max(s0, i - HALF);
    const int end   = min(e0, i + HALF);      // exclusive; valid count in [65,128]
    const int off   = start - w_lo;

    bool val[4];
#pragma unroll
    for (int q = 0; q < 4; q++)
        val[q] = (start + q * 32 + lane) < end;

    float attn[4] = {0.f, 0.f, 0.f, 0.f};
#pragma unroll
    for (int hh = 0; hh < NHEAD; hh++) {
        const float* srow = Ssm + (size_t)(hh * NPB + w) * SROW + off;
        float e[4];
        float s = 0.f;
#pragma unroll
        for (int q = 0; q < 4; q++) {
            float a = val[q] ? srow[q * 32 + lane] : 0.f;  // pad slots -> score 0
            e[q] = __expf(a);                              // pad -> exactly 1
            s += e[q];
        }
#pragma unroll
        for (int o = 16; o > 0; o >>= 1)
            s += __shfl_xor_sync(0xffffffffu, s, o);
        float rs = __fdividef(1.f, s);
#pragma unroll
        for (int q = 0; q < 4; q++) attn[q] += e[q] * rs;
    }

    // keys: valid slots have attn > 0, so raw float bits are order-isomorphic
    // as u32; invalid slots get key 0. attn*0.25 <= 1.0 -> bits 31,30 are 0.
    unsigned u[4];
#pragma unroll
    for (int q = 0; q < 4; q++)
        u[q] = val[q] ? __float_as_uint(attn[q] * 0.25f) : 0u;

    // radix descent: find T = 32nd-largest key (exact)
    unsigned T = 0;
#pragma unroll 1
    for (int bit = 29; bit >= 0; --bit) {
        unsigned cand = T | (1u << bit);
        int c = (u[0] >= cand) + (u[1] >= cand) + (u[2] >= cand) + (u[3] >= cand);
        c = __reduce_add_sync(0xffffffffu, c);
        if (c >= TOPK) T = cand;
    }

    // select: everything > T, plus ties == T filled in ascending slot order
    // (matches jax.lax.top_k's smaller-index-first tie rule)
    int gt = (u[0] > T) + (u[1] > T) + (u[2] > T) + (u[3] > T);
    int rem = TOPK - __reduce_add_sync(0xffffffffu, gt);

    const size_t rowbase = (size_t)i * NN + start;
#pragma unroll
    for (int q = 0; q < 4; q++) {
        bool eq = (u[q] == T);
        unsigned meq = __ballot_sync(0xffffffffu, eq);
        int before = __popc(meq & ((1u << lane) - 1u));
        bool sel = (u[q] > T) || (eq && before < rem);
        if (sel) out[rowbase + q * 32 + lane] = 1.0f;
        int tk = __popc(meq);
        rem -= (tk < rem) ? tk : rem;
    }
}

// ---------------------------------------------------------------------------
extern "C" void kernel_launch(void* const* d_in, const int* in_sizes, int n_in,
                              void* d_out, int out_size)
{
    (void)in_sizes; (void)n_in; (void)out_size;
    const float* X  = (const float*)d_in[0];
    const float* Wq = (const float*)d_in[1];
    const float* bq = (const float*)d_in[2];
    const float* Wk = (const float*)d_in[3];
    const float* bk = (const float*)d_in[4];
    float* out = (float*)d_out;

    // 1) Q||K projection GEMM + interleaved zero-fill of the 4096x4096 output
    dim3 ggrid(512 / GBN, NN / GBM);          // (8, 64) = 512 blocks
    gemm_qk_kernel<<<ggrid, GTHR>>>(X, Wq, bq, Wk, bk, (float4*)out);

    // 2) attention score GEMM + softmax + exact top-32 scatter
    const int smem_bytes = (MAXR * KSTRB + NPB * QROW) * (int)sizeof(float);
    cudaFuncSetAttribute(attn_topk_kernel,
                         cudaFuncAttributeMaxDynamicSharedMemorySize, smem_bytes);
    attn_topk_kernel<<<NN / NPB, ATHR, smem_bytes>>>(out);
}

// round 14
// speedup vs baseline: 1.8357x; 1.0169x over previous
#include <cuda_runtime.h>
#include <math.h>

// Problem constants (fixed by setup_inputs)
#define NN    4096
#define INF_  256
#define SEG   512
#define HALF  64
#define WIN   128
#define NHEAD 4
#define HD    64
#define TOPK  32

// attention kernel tiling
#define NPB   32             // nodes per block
#define ATHR  1024           // attention threads per block (32 warps)
#define MAXR  160            // K rows copied per block (window union <=159, slack-padded)
#define KSTRB 282            // K row stride (floats) in BOTH g_K and smem; conflict-free LDS.64
#define QROW  256
#define SROW  164            // score row stride

#define KCP_BYTES (MAXR * KSTRB * 4)          // 180480, multiple of 16
#define QCP_BYTES (NPB * QROW * 4)            // 32768
#define CP_TOTAL  (KCP_BYTES + QCP_BYTES)     // 213248

// GEMM tiling
#define GBM 64
#define GBN 64
#define GBK 16
#define GTHR 128
#define ASTR 68              // padded smem stride (272B rows, 16B aligned)
#define NTILE (INF_ / GBK)   // 16 k-tiles

// scratch: Q and K projections. g_K is stored PRE-PADDED at stride KSTRB so a
// block's K window is one contiguous blob for cp.async.bulk; 64 slack rows let
// every block copy a fixed MAXR rows.
__device__ float g_Q[(size_t)NN * QROW];
__device__ float g_K[(size_t)(NN + 64) * KSTRB];

// ---------------------------------------------------------------------------
// packed fp32x2 helpers (sm_100+: fma.rn.f32x2 — 2 IEEE fp32 FMAs per issue)
// ---------------------------------------------------------------------------
__device__ __forceinline__ unsigned long long pk2(float x, float y) {
    unsigned long long r;
    asm("mov.b64 %0, {%1, %2};" : "=l"(r) : "f"(x), "f"(y));
    return r;
}
__device__ __forceinline__ void upk2(float& x, float& y, unsigned long long r) {
    asm("mov.b64 {%0, %1}, %2;" : "=f"(x), "=f"(y) : "l"(r));
}
__device__ __forceinline__ unsigned long long fma2(unsigned long long a,
                                                   unsigned long long b,
                                                   unsigned long long c) {
    unsigned long long d;
    asm("fma.rn.f32x2 %0, %1, %2, %3;" : "=l"(d) : "l"(a), "l"(b), "l"(c));
    return d;
}

// ---------------------------------------------------------------------------
// fused Q||K projection GEMM:  [Q|K] = X[4096,256] @ [Wq|Wk] + [bq|bk]
// BM=64, BN=64, BK=16, 128 threads, 8x4 per thread, double-buffered smem,
// interleaved zero-fill of the output matrix. Q half -> g_Q (stride 256,
// float4 stores); K half -> g_K (stride 282, float2 stores: rows 8B-aligned).
// ---------------------------------------------------------------------------
__global__ __launch_bounds__(GTHR) void gemm_qk_kernel(
    const float* __restrict__ X,
    const float* __restrict__ Wq, const float* __restrict__ bq,
    const float* __restrict__ Wk, const float* __restrict__ bk,
    float4* __restrict__ out4)
{
    __shared__ float As[2][GBK][ASTR];   // transposed A tile [k][m]
    __shared__ float Bs[2][GBK][ASTR];   // B tile [k][n]

    const int tid = threadIdx.x;

    const int brow = blockIdx.y * GBM;
    const int bcol = blockIdx.x * GBN;

    // each block lies entirely in the Q half (bcol<256) or K half
    const bool isQ    = (bcol < 256);
    const float* W    = isQ ? Wq : Wk;
    const float* bias = isQ ? bq : bk;
    const int wcol = bcol & 255;

    // zero-fill slice: block zb covers 8 rows (2048 float4) of the output
    const int zb = blockIdx.y * gridDim.x + blockIdx.x;   // 0..511
    float4* zdst = out4 + (size_t)zb * (8 * NN / 4);
    const float4 zv = make_float4(0.f, 0.f, 0.f, 0.f);

    const int tx = tid & 15;          // n0 = tx*4
    const int ty = tid >> 4;          // m0 = ty*8
    const int m0 = ty * 8;
    const int n0 = tx * 4;

    // prefetch registers
    float4 xa[2], xb[2];

    // ---- load tile 0 into registers (LDGs first, in flight ASAP)
#pragma unroll
    for (int t = 0; t < 2; t++) {
        int f = tid + t * GTHR;
        int r = f >> 2;
        int c = (f & 3) << 2;
        xa[t] = *(const float4*)(X + (size_t)(brow + r) * INF_ + c);
        int rb = f >> 4;
        int cb = (f & 15) << 2;
        xb[t] = *(const float4*)(W + (size_t)rb * 256 + wcol + cb);
    }
    // store tile 0 to buffer 0
#pragma unroll
    for (int t = 0; t < 2; t++) {
        int f = tid + t * GTHR;
        int r = f >> 2;
        int c = (f & 3) << 2;
        As[0][c + 0][r] = xa[t].x;
        As[0][c + 1][r] = xa[t].y;
        As[0][c + 2][r] = xa[t].z;
        As[0][c + 3][r] = xa[t].w;
        int rb = f >> 4;
        int cb = (f & 15) << 2;
        *(float4*)&Bs[0][rb][cb] = xb[t];
    }
    __syncthreads();

    unsigned long long acc2[4][4];    // [m-pair][n]
#pragma unroll
    for (int a = 0; a < 4; a++)
#pragma unroll
        for (int b = 0; b < 4; b++) acc2[a][b] = 0ULL;

#pragma unroll
    for (int it = 0; it < NTILE; it++) {
        const int cur = it & 1;

        // issue next tile's LDGs early (latency hidden by the math below)
        if (it + 1 < NTILE) {
            const int k0 = (it + 1) * GBK;
#pragma unroll
            for (int t = 0; t < 2; t++) {
                int f = tid + t * GTHR;
                int r = f >> 2;
                int c = (f & 3) << 2;
                xa[t] = *(const float4*)(X + (size_t)(brow + r) * INF_ + k0 + c);
                int rb = f >> 4;
                int cb = (f & 15) << 2;
                xb[t] = *(const float4*)(W + (size_t)(k0 + rb) * 256 + wcol + cb);
            }
        }

        // one slice of the output zero-fill per iteration (overlaps compute)
        zdst[it * GTHR + tid] = zv;

        // math on current buffer
#pragma unroll
        for (int k = 0; k < GBK; k++) {
            float a[8], b[4];
            *(float4*)&a[0] = *(float4*)&As[cur][k][m0];
            *(float4*)&a[4] = *(float4*)&As[cur][k][m0 + 4];
            *(float4*)&b[0] = *(float4*)&Bs[cur][k][n0];
            unsigned long long a2[4];
            a2[0] = pk2(a[0], a[1]);
            a2[1] = pk2(a[2], a[3]);
            a2[2] = pk2(a[4], a[5]);
            a2[3] = pk2(a[6], a[7]);
            unsigned long long bd[4];
            bd[0] = pk2(b[0], b[0]);
            bd[1] = pk2(b[1], b[1]);
            bd[2] = pk2(b[2], b[2]);
            bd[3] = pk2(b[3], b[3]);
#pragma unroll
            for (int mp = 0; mp < 4; mp++)
#pragma unroll
                for (int n = 0; n < 4; n++)
                    acc2[mp][n] = fma2(a2[mp], bd[n], acc2[mp][n]);
        }

        // stage next tile into the other buffer (safe: last reads of that
        // buffer were ordered by the previous __syncthreads)
        if (it + 1 < NTILE) {
            const int nxt = cur ^ 1;
#pragma unroll
            for (int t = 0; t < 2; t++) {
                int f = tid + t * GTHR;
                int r = f >> 2;
                int c = (f & 3) << 2;
                As[nxt][c + 0][r] = xa[t].x;
                As[nxt][c + 1][r] = xa[t].y;
                As[nxt][c + 2][r] = xa[t].z;
                As[nxt][c + 3][r] = xa[t].w;
                int rb = f >> 4;
                int cb = (f & 15) << 2;
                *(float4*)&Bs[nxt][rb][cb] = xb[t];
            }
            __syncthreads();
        }
    }

    // epilogue: unpack, +bias, store two rows per m-pair
    float4 bv = *(const float4*)(bias + wcol + n0);
#pragma unroll
    for (int mp = 0; mp < 4; mp++) {
        float lo[4], hi[4];
#pragma unroll
        for (int n = 0; n < 4; n++) upk2(lo[n], hi[n], acc2[mp][n]);
        int r0 = brow + m0 + 2 * mp;
        float4 v0, v1;
        v0.x = lo[0] + bv.x; v0.y = lo[1] + bv.y; v0.z = lo[2] + bv.z; v0.w = lo[3] + bv.w;
        v1.x = hi[0] + bv.x; v1.y = hi[1] + bv.y; v1.z = hi[2] + bv.z; v1.w = hi[3] + bv.w;
        if (isQ) {
            *(float4*)(g_Q + (size_t)r0 * QROW + bcol + n0) = v0;
            *(float4*)(g_Q + (size_t)(r0 + 1) * QROW + bcol + n0) = v1;
        } else {
            const int col = wcol + n0;
            float* d0 = g_K + (size_t)r0 * KSTRB + col;
            float* d1 = g_K + (size_t)(r0 + 1) * KSTRB + col;
            *(float2*)(d0)     = make_float2(v0.x, v0.y);
            *(float2*)(d0 + 2) = make_float2(v0.z, v0.w);
            *(float2*)(d1)     = make_float2(v1.x, v1.y);
            *(float2*)(d1 + 2) = make_float2(v1.z, v1.w);
        }
    }
}

// ---------------------------------------------------------------------------
// Attention: phase A is now TWO cp.async.bulk copies (K window: one
// contiguous pre-padded blob from g_K; Q rows from g_Q) completing on one
// mbarrier — zero LSU-issue pressure. Phases B and C are byte-identical to
// the previously passing kernel: register-tiled score GEMM (1 head x
// 4 nodes x 5 rows, LDS.64) then warp-per-node softmax (unmasked zero-
// padding, as the reference) + exact top-32 + parallel scatter of 1.0f.
// ---------------------------------------------------------------------------
__global__ __launch_bounds__(ATHR) void attn_topk_kernel(float* __restrict__ out)
{
    extern __shared__ float smem[];
    float* Ksm = smem;                        // [MAXR][KSTRB]
    float* Qsm = smem + MAXR * KSTRB;         // [NPB][QROW] (offset 180480 B, 16B-aligned)
    float* Ssm = smem;                        // aliases Ksm after phase B: [4*NPB][SROW]
    __shared__ __align__(8) unsigned long long mbar_storage;

    const int tid  = threadIdx.x;
    const int i0   = blockIdx.x * NPB;
    const int s0   = i0 & ~(SEG - 1);
    const int e0   = s0 + SEG;
    const int w_lo = max(s0, i0 - HALF);      // multiple of 32

    // ---- phase A: bulk-copy K window (fixed MAXR rows; slack rows unused)
    // and Q rows into smem via one mbarrier.
    const unsigned mbar = (unsigned)__cvta_generic_to_shared(&mbar_storage);
    if (tid == 0)
        asm volatile("mbarrier.init.shared.b64 [%0], 1;" :: "r"(mbar) : "memory");
    __syncthreads();
    if (tid == 0) {
        asm volatile("mbarrier.arrive.expect_tx.shared.b64 _, [%0], %1;"
                     :: "r"(mbar), "r"((unsigned)CP_TOTAL) : "memory");
        const unsigned ksm = (unsigned)__cvta_generic_to_shared(Ksm);
        const unsigned qsm = (unsigned)__cvta_generic_to_shared(Qsm);
        const float* ksrc = g_K + (size_t)w_lo * KSTRB;   // 16B-aligned (w_lo even)
        const float* qsrc = g_Q + (size_t)i0 * QROW;      // 16B-aligned
        asm volatile(
            "cp.async.bulk.shared::cta.global.mbarrier::complete_tx::bytes [%0], [%1], %2, [%3];"
            :: "r"(ksm), "l"(ksrc), "r"((unsigned)KCP_BYTES), "r"(mbar) : "memory");
        asm volatile(
            "cp.async.bulk.shared::cta.global.mbarrier::complete_tx::bytes [%0], [%1], %2, [%3];"
            :: "r"(qsm), "l"(qsrc), "r"((unsigned)QCP_BYTES), "r"(mbar) : "memory");
    }
    // all threads wait for both copies (phase parity 0)
    asm volatile(
        "{\n\t"
        ".reg .pred P;\n\t"
        "WAIT_%=:\n\t"
        "mbarrier.try_wait.parity.acquire.cta.shared::cta.b64 P, [%0], 0;\n\t"
        "@!P bra WAIT_%=;\n\t"
        "}"
        :: "r"(mbar) : "memory");

    // ---- phase B: score GEMM. thread -> (head h, node-quad ng, row-5 rg)
    const int rg = tid & 31;                  // rows rg*5 .. rg*5+4
    const int ng = (tid >> 5) & 7;            // nodes ng*4 .. ng*4+3
    const int h  = tid >> 8;                  // head

    const float* kb = Ksm + (rg * 5) * KSTRB + h * HD;
    const float* qb = Qsm + (ng * 4) * QROW + h * HD;

    unsigned long long acc[4][5];
#pragma unroll
    for (int a = 0; a < 4; a++)
#pragma unroll
        for (int r = 0; r < 5; r++) acc[a][r] = 0ULL;

#pragma unroll
    for (int d2 = 0; d2 < 32; d2++) {         // 2 floats per step
        unsigned long long qd[4];
#pragma unroll
        for (int a = 0; a < 4; a++)           // warp-broadcast LDS.64
            qd[a] = *(const unsigned long long*)(qb + a * QROW + d2 * 2);
#pragma unroll
        for (int r = 0; r < 5; r++) {
            unsigned long long kv =
                *(const unsigned long long*)(kb + r * KSTRB + d2 * 2);
#pragma unroll
            for (int a = 0; a < 4; a++)
                acc[a][r] = fma2(kv, qd[a], acc[a][r]);
        }
    }

    float sc[4][5];
#pragma unroll
    for (int a = 0; a < 4; a++)
#pragma unroll
        for (int r = 0; r < 5; r++) {
            float lo, hi;
            upk2(lo, hi, acc[a][r]);
            sc[a][r] = (lo + hi) * 0.25f;     // /sqrt(64)/tau
        }
    __syncthreads();   // all K reads done; Ksm region now reusable

    // write scores: Ssm[(h*32 + node)][row]
#pragma unroll
    for (int a = 0; a < 4; a++) {
        float* dst = Ssm + (size_t)(h * NPB + ng * 4 + a) * SROW + rg * 5;
#pragma unroll
        for (int r = 0; r < 5; r++) dst[r] = sc[a][r];
    }
    __syncthreads();

    // ---- phase C: warp-per-node softmax + exact top-32
    const int w    = tid >> 5;
    const int lane = tid & 31;
    const int i    = i0 + w;
    const int start = max(s0, i - HALF);
    const int end   = min(e0, i + HALF);      // exclusive; valid count in [65,128]
    const int off   = start - w_lo;

    bool val[4];
#pragma unroll
    for (int q = 0; q < 4; q++)
        val[q] = (start + q * 32 + lane) < end;

    float attn[4] = {0.f, 0.f, 0.f, 0.f};
#pragma unroll
    for (int hh = 0; hh < NHEAD; hh++) {
        const float* srow = Ssm + (size_t)(hh * NPB + w) * SROW + off;
        float e[4];
        float s = 0.f;
#pragma unroll
        for (int q = 0; q < 4; q++) {
            float a = val[q] ? srow[q * 32 + lane] : 0.f;  // pad slots -> score 0
            e[q] = __expf(a);                              // pad -> exactly 1
            s += e[q];
        }
#pragma unroll
        for (int o = 16; o > 0; o >>= 1)
            s += __shfl_xor_sync(0xffffffffu, s, o);
        float rs = __fdividef(1.f, s);
#pragma unroll
        for (int q = 0; q < 4; q++) attn[q] += e[q] * rs;
    }

    // keys: valid slots have attn > 0, so raw float bits are order-isomorphic
    // as u32; invalid slots get key 0. attn*0.25 <= 1.0 -> bits 31,30 are 0.
    unsigned u[4];
#pragma unroll
    for (int q = 0; q < 4; q++)
        u[q] = val[q] ? __float_as_uint(attn[q] * 0.25f) : 0u;

    // radix descent: find T = 32nd-largest key (exact)
    unsigned T = 0;
#pragma unroll 1
    for (int bit = 29; bit >= 0; --bit) {
        unsigned cand = T | (1u << bit);
        int c = (u[0] >= cand) + (u[1] >= cand) + (u[2] >= cand) + (u[3] >= cand);
        c = __reduce_add_sync(0xffffffffu, c);
        if (c >= TOPK) T = cand;
    }

    // select: everything > T, plus ties == T filled in ascending slot order
    // (matches jax.lax.top_k's smaller-index-first tie rule)
    int gt = (u[0] > T) + (u[1] > T) + (u[2] > T) + (u[3] > T);
    int rem = TOPK - __reduce_add_sync(0xffffffffu, gt);

    const size_t rowbase = (size_t)i * NN + start;
#pragma unroll
    for (int q = 0; q < 4; q++) {
        bool eq = (u[q] == T);
        unsigned meq = __ballot_sync(0xffffffffu, eq);
        int before = __popc(meq & ((1u << lane) - 1u));
        bool sel = (u[q] > T) || (eq && before < rem);
        if (sel) out[rowbase + q * 32 + lane] = 1.0f;
        int tk = __popc(meq);
        rem -= (tk < rem) ? tk : rem;
    }
}

// ---------------------------------------------------------------------------
extern "C" void kernel_launch(void* const* d_in, const int* in_sizes, int n_in,
                              void* d_out, int out_size)
{
    (void)in_sizes; (void)n_in; (void)out_size;
    const float* X  = (const float*)d_in[0];
    const float* Wq = (const float*)d_in[1];
    const float* bq = (const float*)d_in[2];
    const float* Wk = (const float*)d_in[3];
    const float* bk = (const float*)d_in[4];
    float* out = (float*)d_out;

    // 1) Q||K projection GEMM + interleaved zero-fill of the 4096x4096 output
    dim3 ggrid(512 / GBN, NN / GBM);          // (8, 64) = 512 blocks
    gemm_qk_kernel<<<ggrid, GTHR>>>(X, Wq, bq, Wk, bk, (float4*)out);

    // 2) attention score GEMM + softmax + exact top-32 scatter
    const int smem_bytes = (MAXR * KSTRB + NPB * QROW) * (int)sizeof(float);
    cudaFuncSetAttribute(attn_topk_kernel,
                         cudaFuncAttributeMaxDynamicSharedMemorySize, smem_bytes);
    attn_topk_kernel<<<NN / NPB, ATHR, smem_bytes>>>(out);
}